// round 15
// baseline (speedup 1.0000x reference)
#include <cuda_runtime.h>
#include <cstdint>

// CoverageAttention GB300 — R13: attention re-tiled to 16 q-rows/CTA so smem
// (111.5 KB) fits 2 CTAs/SM — co-resident CTA hides sync/wait stalls.
// GEMMs unchanged (R12). B=8, Tq=Tk=1024, d_model=1024, H=16, hd=64, SCALE=8.

#define NB   8
#define NH   16
#define NT   1024
#define NDM  1024
#define NHD  64

__device__ float g_Q[NB * NH * NT * NHD];
__device__ float g_K[NB * NH * NT * NHD];
__device__ float g_V[NB * NH * NT * NHD];
__device__ float g_O[NB * NT * NDM];
__device__ float g_covacc[NB * NT];
__device__ float g_W4[4][NDM * NDM];          // rounded Wq,Wk,Wv,Wo
__device__ float g_X[2][NB * NT * NDM];       // rounded query, memory

__global__ void zero_covacc_kernel() {
    int i = blockIdx.x * 256 + threadIdx.x;
    if (i < NB * NT) g_covacc[i] = 0.0f;
}

__device__ __forceinline__ uint32_t smem_u32(const void* p) {
    uint32_t a;
    asm("{ .reg .u64 t; cvta.to.shared.u64 t, %1; cvt.u32.u64 %0, t; }" : "=r"(a) : "l"(p));
    return a;
}
__device__ __forceinline__ uint32_t f2tf32(float x) {
    uint32_t r;
    asm("cvt.rna.tf32.f32 %0, %1;" : "=r"(r) : "f"(x));
    return r;
}
__device__ __forceinline__ float roundtf(float x) {
    return __uint_as_float(f2tf32(x));
}
__device__ __forceinline__ void mma_tf32(float c[4],
                                         uint32_t a0, uint32_t a1, uint32_t a2, uint32_t a3,
                                         uint32_t b0, uint32_t b1) {
    asm volatile(
        "mma.sync.aligned.m16n8k8.row.col.f32.tf32.tf32.f32 "
        "{%0,%1,%2,%3}, {%4,%5,%6,%7}, {%8,%9}, {%0,%1,%2,%3};"
        : "+f"(c[0]), "+f"(c[1]), "+f"(c[2]), "+f"(c[3])
        : "r"(a0), "r"(a1), "r"(a2), "r"(a3), "r"(b0), "r"(b1));
}

#define CP16(dst, src) \
    asm volatile("cp.async.cg.shared.global [%0], [%1], 16;" :: "r"(dst), "l"(src) : "memory")
#define CPC() asm volatile("cp.async.commit_group;" ::: "memory")
#define CPW(n) asm volatile("cp.async.wait_group %0;" :: "n"(n) : "memory")

// ---------------- pre-round inputs to tf32 ----------------
__global__ void round_inputs_kernel(
    const float4* __restrict__ Wq, const float4* __restrict__ Wk,
    const float4* __restrict__ Wv, const float4* __restrict__ Wo,
    const float4* __restrict__ q,  const float4* __restrict__ mem)
{
    int idx = blockIdx.x * 256 + threadIdx.x;
    if (idx >= 5242880) return;
    float4 v;
    float* dst;
    if (idx < 1048576) {
        int wi = idx >> 18;
        int off = idx & 0x3FFFF;
        const float4* src = (wi == 0) ? Wq : (wi == 1) ? Wk : (wi == 2) ? Wv : Wo;
        v = src[off];
        dst = &g_W4[wi][off * 4];
    } else {
        int j = idx - 1048576;
        int xi = j >> 21;
        int off = j & 0x1FFFFF;
        v = (xi == 0) ? q[off] : mem[off];
        dst = &g_X[xi][off * 4];
    }
    float4 r;
    r.x = roundtf(v.x); r.y = roundtf(v.y); r.z = roundtf(v.z); r.w = roundtf(v.w);
    *(float4*)dst = r;
}

// ================= tf32 GEMM, cp.async 3-stage (unchanged from R12) =========
#define G_SMEM_BYTES 61440

template <bool HEADED, bool ROUND_OUT>
__device__ __forceinline__ void gemm_body(
    const float* __restrict__ Ap, const float* __restrict__ W,
    const float* __restrict__ bias, float* __restrict__ dst,
    int bm, int bn)
{
    extern __shared__ float gsm[];
    float (*As)[128][20] = (float(*)[128][20])(gsm);
    float (*Ws)[128][20] = (float(*)[128][20])(gsm + 3 * 2560);
    uint32_t sbA = smem_u32(&As[0][0][0]);
    uint32_t sbW = smem_u32(&Ws[0][0][0]);

    int tid = threadIdx.x;
    int lane = tid & 31;
    int wid = tid >> 5;
    int warp_m = wid & 1;
    int warp_n = wid >> 1;
    int g = lane >> 2;
    int t = lane & 3;

    int lr = tid >> 1;
    int kc = (tid & 1) * 8;
    const float* aP = Ap + (size_t)(bm + lr) * NDM + kc;
    const float* wP = W  + (size_t)(bn + lr) * NDM + kc;
    uint32_t dA = sbA + (lr * 20 + kc) * 4;
    uint32_t dW = sbW + (lr * 20 + kc) * 4;

    float c[4][4][4];
#pragma unroll
    for (int mi = 0; mi < 4; mi++)
#pragma unroll
        for (int ni = 0; ni < 4; ni++)
#pragma unroll
            for (int e = 0; e < 4; e++) c[mi][ni][e] = 0.0f;

#pragma unroll
    for (int s = 0; s < 2; s++) {
        CP16(dA + s * 10240, aP + s * 16);
        CP16(dA + s * 10240 + 16, aP + s * 16 + 4);
        CP16(dW + s * 10240, wP + s * 16);
        CP16(dW + s * 10240 + 16, wP + s * 16 + 4);
        CPC();
    }

    for (int kt = 0; kt < 64; kt++) {
        if (kt < 63) { CPW(1); } else { CPW(0); }
        __syncthreads();
        int slot = kt - (kt / 3) * 3;

        if (kt + 2 < 64) {
            int ns = (kt + 2) - ((kt + 2) / 3) * 3;
            CP16(dA + ns * 10240, aP + (kt + 2) * 16);
            CP16(dA + ns * 10240 + 16, aP + (kt + 2) * 16 + 4);
            CP16(dW + ns * 10240, wP + (kt + 2) * 16);
            CP16(dW + ns * 10240 + 16, wP + (kt + 2) * 16 + 4);
            CPC();
        }

        const float (*Ac)[20] = As[slot];
        const float (*Wc)[20] = Ws[slot];
#pragma unroll
        for (int kk = 0; kk < 16; kk += 8) {
            uint32_t af[4][4];
#pragma unroll
            for (int mi = 0; mi < 4; mi++) {
                int r0 = warp_m * 64 + mi * 16 + g;
                af[mi][0] = __float_as_uint(Ac[r0][kk + t]);
                af[mi][1] = __float_as_uint(Ac[r0 + 8][kk + t]);
                af[mi][2] = __float_as_uint(Ac[r0][kk + t + 4]);
                af[mi][3] = __float_as_uint(Ac[r0 + 8][kk + t + 4]);
            }
            uint32_t bf[4][2];
#pragma unroll
            for (int ni = 0; ni < 4; ni++) {
                int c0 = warp_n * 32 + ni * 8 + g;
                bf[ni][0] = __float_as_uint(Wc[c0][kk + t]);
                bf[ni][1] = __float_as_uint(Wc[c0][kk + t + 4]);
            }
#pragma unroll
            for (int mi = 0; mi < 4; mi++)
#pragma unroll
                for (int ni = 0; ni < 4; ni++)
                    mma_tf32(c[mi][ni], af[mi][0], af[mi][1], af[mi][2], af[mi][3],
                             bf[ni][0], bf[ni][1]);
        }
    }

#pragma unroll
    for (int mi = 0; mi < 4; mi++) {
#pragma unroll
        for (int ni = 0; ni < 4; ni++) {
            int n0 = bn + warp_n * 32 + ni * 8 + t * 2;
            float b0v = __ldg(bias + n0);
            float b1v = __ldg(bias + n0 + 1);
#pragma unroll
            for (int rh = 0; rh < 2; rh++) {
                int m = bm + warp_m * 64 + mi * 16 + g + rh * 8;
                float v0 = c[mi][ni][rh * 2 + 0] + b0v;
                float v1 = c[mi][ni][rh * 2 + 1] + b1v;
                if (ROUND_OUT) { v0 = roundtf(v0); v1 = roundtf(v1); }
                if (HEADED) {
                    int bb = m >> 10, tok = m & 1023;
                    size_t base = (((size_t)(bb * NH + (n0 >> 6))) * NT + tok) * NHD + (n0 & 63);
                    dst[base] = v0; dst[base + 1] = v1;
                } else {
                    dst[(size_t)m * NDM + n0] = v0;
                    dst[(size_t)m * NDM + n0 + 1] = v1;
                }
            }
        }
    }
}

__global__ __launch_bounds__(256, 2) void qkv_gemm(
    const float* __restrict__ bq, const float* __restrict__ bk,
    const float* __restrict__ bv)
{
    int z = blockIdx.z;
    const float* A = (z == 0) ? g_X[0] : g_X[1];
    const float* W = g_W4[z];
    const float* bias = (z == 0) ? bq : (z == 1) ? bk : bv;
    float* dst = (z == 0) ? g_Q : (z == 1) ? g_K : g_V;
    gemm_body<true, true>(A, W, bias, dst, blockIdx.y * 128, blockIdx.x * 128);
}

__global__ __launch_bounds__(256, 2) void out_gemm(
    const float* __restrict__ bo, float* __restrict__ Cout)
{
    gemm_body<false, false>((const float*)g_O, g_W4[3], bo, Cout,
                            blockIdx.y * 128, blockIdx.x * 128);
}

// ================= attention: 16 q-rows/CTA, 2 CTAs/SM =================
// 64-token K/V tiles, 2 buffers. K stride 68 (phase1 conflict-free:
// bank = 4g+t distinct), V stride 72 (phase4 conflict-free: 8tok+t distinct).
#define SROW    1033
#define OFF_S   0                    // 16 x 1033 = 16528
#define OFF_KV0 16528                // 64 x 72 = 4608
#define OFF_KV1 21136                // 64 x 72 = 4608
#define OFF_QS  25744                // 16 x 68 = 1088
#define OFF_C   26832                // 1024
#define OFF_R   27856                // 16
#define A_SMEM_FLOATS 27872
#define A_SMEM_BYTES  (A_SMEM_FLOATS * 4)   // 111488

__global__ __launch_bounds__(256, 2) void attn_mma(
    const float* __restrict__ coverage, const float* __restrict__ Wcov)
{
    extern __shared__ float sm[];
    uint32_t sb = smem_u32(sm);
    int tid = threadIdx.x;
    int lane = tid & 31, wid = tid >> 5;
    int g = lane >> 2, t = lane & 3;
    int bh = blockIdx.y, b = bh >> 4, h = bh & 15;
    int q0 = blockIdx.x * 16;
    float wcov = Wcov[h];

    const float* Qb = g_Q + (size_t)bh * NT * NHD + (size_t)q0 * NHD;
    const float* Kb = g_K + (size_t)bh * NT * NHD;
    const float* Vb = g_V + (size_t)bh * NT * NHD;

    // ---- prologue: Q (16x64) + cov + K tiles 0,1 (64 tokens each) ----
    {
        int q = tid >> 4, c4 = tid & 15;
        CP16(sb + (OFF_QS + q * 68 + c4 * 4) * 4, Qb + q * 64 + c4 * 4);
    }
    CP16(sb + (OFF_C + tid * 4) * 4, coverage + b * NT + tid * 4);
#pragma unroll
    for (int i = 0; i < 4; i++) {
        int id = tid + 256 * i;
        int tok = id >> 4, c4 = id & 15;
        CP16(sb + (OFF_KV0 + tok * 68 + c4 * 4) * 4, Kb + tok * 64 + c4 * 4);
    }
    CPC();
#pragma unroll
    for (int i = 0; i < 4; i++) {
        int id = tid + 256 * i;
        int tok = id >> 4, c4 = id & 15;
        CP16(sb + (OFF_KV1 + tok * 68 + c4 * 4) * 4, Kb + (64 + tok) * 64 + c4 * 4);
    }
    CPC();
    CPW(1);
    __syncthreads();

    for (int i = tid; i < NT; i += 256) sm[OFF_C + i] *= wcov;

    // Q fragments: one m16 tile (16 q-rows), raw tf32 bits
    uint32_t qf[8][4];
#pragma unroll
    for (int kk = 0; kk < 8; kk++) {
        int base = OFF_QS + g * 68 + kk * 8 + t;
        qf[kk][0] = __float_as_uint(sm[base]);
        qf[kk][1] = __float_as_uint(sm[base + 8 * 68]);
        qf[kk][2] = __float_as_uint(sm[base + 4]);
        qf[kk][3] = __float_as_uint(sm[base + 8 * 68 + 4]);
    }
    __syncthreads();   // cov scaling done before S epilogue reads it

    // -------- phase 1: S = QK^T/8 + cov; 16 iters; warp owns 8 tokens --------
    int tokb = wid * 8;
    for (int kt = 0; kt < 16; kt++) {
        if (kt) {
            if (kt < 15) { CPW(1); } else { CPW(0); }
            __syncthreads();
        }
        const float* Ks = sm + ((kt & 1) ? OFF_KV1 : OFF_KV0);
        const float* kr = Ks + (tokb + g) * 68 + t;
        float se[4] = {0, 0, 0, 0}, so[4] = {0, 0, 0, 0};
#pragma unroll
        for (int kk = 0; kk < 8; kk += 2) {
            uint32_t b0 = __float_as_uint(kr[kk * 8]);
            uint32_t b1 = __float_as_uint(kr[kk * 8 + 4]);
            uint32_t d0 = __float_as_uint(kr[kk * 8 + 8]);
            uint32_t d1 = __float_as_uint(kr[kk * 8 + 12]);
            mma_tf32(se, qf[kk][0], qf[kk][1], qf[kk][2], qf[kk][3], b0, b1);
            mma_tf32(so, qf[kk+1][0], qf[kk+1][1], qf[kk+1][2], qf[kk+1][3], d0, d1);
        }
        int kgl = kt * 64 + tokb + 2 * t;
        float cv0 = sm[OFF_C + kgl], cv1 = sm[OFF_C + kgl + 1];
        sm[OFF_S + g * SROW + kgl]           = (se[0] + so[0]) * 0.125f + cv0;
        sm[OFF_S + g * SROW + kgl + 1]       = (se[1] + so[1]) * 0.125f + cv1;
        sm[OFF_S + (g + 8) * SROW + kgl]     = (se[2] + so[2]) * 0.125f + cv0;
        sm[OFF_S + (g + 8) * SROW + kgl + 1] = (se[3] + so[3]) * 0.125f + cv1;
        __syncthreads();
        if (kt < 14) {
            uint32_t dof = (kt & 1) ? OFF_KV1 : OFF_KV0;
#pragma unroll
            for (int i = 0; i < 4; i++) {
                int id = tid + 256 * i;
                int tok = id >> 4, c4 = id & 15;
                CP16(sb + (dof + tok * 68 + c4 * 4) * 4,
                     Kb + ((kt + 2) * 64 + tok) * 64 + c4 * 4);
            }
            CPC();
        }
    }

    // issue V tiles 0,1 (stride 72; hidden under softmax)
#pragma unroll
    for (int i = 0; i < 4; i++) {
        int id = tid + 256 * i;
        int tok = id >> 4, c4 = id & 15;
        CP16(sb + (OFF_KV0 + tok * 72 + c4 * 4) * 4, Vb + tok * 64 + c4 * 4);
    }
    CPC();
#pragma unroll
    for (int i = 0; i < 4; i++) {
        int id = tid + 256 * i;
        int tok = id >> 4, c4 = id & 15;
        CP16(sb + (OFF_KV1 + tok * 72 + c4 * 4) * 4, Vb + (64 + tok) * 64 + c4 * 4);
    }
    CPC();

    // -------- phase 2: softmax (no max pass) + round P --------
    for (int q = wid; q < 16; q += 8) {
        float* row = &sm[OFF_S + q * SROW];
        float l = 0.0f;
        for (int k = lane; k < NT; k += 32) {
            float e = __expf(row[k]);
            row[k] = roundtf(e);
            l += e;
        }
#pragma unroll
        for (int o = 16; o > 0; o >>= 1) l += __shfl_xor_sync(0xffffffff, l, o);
        if (lane == 0) sm[OFF_R + q] = 1.0f / l;
    }
    __syncthreads();

    // -------- phase 3: coverage column sums --------
    for (int k = tid; k < NT; k += 256) {
        float s = 0.0f;
#pragma unroll
        for (int q = 0; q < 16; q++)
            s += sm[OFF_S + q * SROW + k] * sm[OFF_R + q];
        atomicAdd(&g_covacc[b * NT + k], s);
    }

    // -------- phase 4: O = P @ V; 16 iters; warps = nh(2) x kp(4) --------
    int nh = wid & 1, kp = wid >> 1;
    float oa[4][4];
#pragma unroll
    for (int nj = 0; nj < 4; nj++)
#pragma unroll
        for (int e = 0; e < 4; e++) oa[nj][e] = 0.0f;

    for (int kt = 0; kt < 16; kt++) {
        if (kt < 15) { CPW(1); } else { CPW(0); }
        __syncthreads();
        const float* Vs = sm + ((kt & 1) ? OFF_KV1 : OFF_KV0);
#pragma unroll
        for (int s = 0; s < 2; s++) {
            int kb = kp * 16 + s * 8;
            int ar = OFF_S + g * SROW + kt * 64 + kb + t;
            uint32_t a0 = __float_as_uint(sm[ar]);
            uint32_t a1 = __float_as_uint(sm[ar + 8 * SROW]);
            uint32_t a2 = __float_as_uint(sm[ar + 4]);
            uint32_t a3 = __float_as_uint(sm[ar + 8 * SROW + 4]);
#pragma unroll
            for (int nj = 0; nj < 4; nj++) {
                int d0 = nh * 32 + nj * 8 + g;
                uint32_t b0 = __float_as_uint(Vs[(kb + t) * 72 + d0]);
                uint32_t b1 = __float_as_uint(Vs[(kb + t + 4) * 72 + d0]);
                mma_tf32(oa[nj], a0, a1, a2, a3, b0, b1);
            }
        }
        __syncthreads();
        if (kt < 14) {
            uint32_t dof = (kt & 1) ? OFF_KV1 : OFF_KV0;
#pragma unroll
            for (int i = 0; i < 4; i++) {
                int id = tid + 256 * i;
                int tok = id >> 4, c4 = id & 15;
                CP16(sb + (dof + tok * 72 + c4 * 4) * 4,
                     Vb + ((kt + 2) * 64 + tok) * 64 + c4 * 4);
            }
            CPC();
        }
    }

    // 4-way kp partial reduction via smem (reuses KV region: 4 x 16 x 68)
    {
        float* op = sm + OFF_KV0 + kp * 1088;
#pragma unroll
        for (int nj = 0; nj < 4; nj++) {
            int col = nh * 32 + nj * 8 + 2 * t;
            op[g * 68 + col]           = oa[nj][0];
            op[g * 68 + col + 1]       = oa[nj][1];
            op[(g + 8) * 68 + col]     = oa[nj][2];
            op[(g + 8) * 68 + col + 1] = oa[nj][3];
        }
    }
    __syncthreads();
#pragma unroll
    for (int e = 0; e < 4; e++) {
        int idx = tid + e * 256;
        int q = idx >> 6, d = idx & 63;
        float val = (sm[OFF_KV0 + q * 68 + d]
                   + sm[OFF_KV0 + 1088 + q * 68 + d]
                   + sm[OFF_KV0 + 2 * 1088 + q * 68 + d]
                   + sm[OFF_KV0 + 3 * 1088 + q * 68 + d]) * sm[OFF_R + q];
        g_O[((size_t)(b * NT + q0 + q)) * NDM + h * 64 + d] = roundtf(val);
    }
}

__global__ void finalize_cov_kernel(const float* __restrict__ coverage,
                                    float* __restrict__ outcov)
{
    int i = blockIdx.x * 256 + threadIdx.x;
    if (i < NB * NT) outcov[i] = coverage[i] + g_covacc[i] * (1.0f / NH);
}

// ================= launcher =================
extern "C" void kernel_launch(void* const* d_in, const int* in_sizes, int n_in,
                              void* d_out, int out_size)
{
    const float* query    = (const float*)d_in[0];
    const float* memory   = (const float*)d_in[1];
    const float* coverage = (const float*)d_in[2];
    const float* Wq       = (const float*)d_in[3];
    const float* bq       = (const float*)d_in[4];
    const float* Wk       = (const float*)d_in[5];
    const float* bk       = (const float*)d_in[6];
    const float* Wv       = (const float*)d_in[7];
    const float* bv       = (const float*)d_in[8];
    const float* Wo       = (const float*)d_in[9];
    const float* bo       = (const float*)d_in[10];
    const float* Wcov     = (const float*)d_in[11];
    float* out = (float*)d_out;

    cudaFuncSetAttribute(qkv_gemm, cudaFuncAttributeMaxDynamicSharedMemorySize, G_SMEM_BYTES);
    cudaFuncSetAttribute(out_gemm, cudaFuncAttributeMaxDynamicSharedMemorySize, G_SMEM_BYTES);
    cudaFuncSetAttribute(attn_mma, cudaFuncAttributeMaxDynamicSharedMemorySize, A_SMEM_BYTES);

    zero_covacc_kernel<<<32, 256>>>();

    round_inputs_kernel<<<(5242880 + 255) / 256, 256>>>(
        (const float4*)Wq, (const float4*)Wk, (const float4*)Wv, (const float4*)Wo,
        (const float4*)query, (const float4*)memory);

    qkv_gemm<<<dim3(NDM / 128, (NB * NT) / 128, 3), 256, G_SMEM_BYTES>>>(bq, bk, bv);

    attn_mma<<<dim3(NT / 16, NB * NH), 256, A_SMEM_BYTES>>>(coverage, Wcov);

    out_gemm<<<dim3(NDM / 128, (NB * NT) / 128), 256, G_SMEM_BYTES>>>(bo, out);

    finalize_cov_kernel<<<32, 256>>>(coverage, out + (size_t)NB * NT * NDM);
}

// round 16
// speedup vs baseline: 1.0881x; 1.0881x over previous
#include <cuda_runtime.h>
#include <cstdint>

// CoverageAttention GB300 — R15: fused attention (S-MMA + exp + in-loop row
// sums + PV-MMA in ONE k-tile loop; standalone softmax pass eliminated).
// GEMMs unchanged (R12). B=8, Tq=Tk=1024, d_model=1024, H=16, hd=64, SCALE=8.

#define NB   8
#define NH   16
#define NT   1024
#define NDM  1024
#define NHD  64

__device__ float g_Q[NB * NH * NT * NHD];
__device__ float g_K[NB * NH * NT * NHD];
__device__ float g_V[NB * NH * NT * NHD];
__device__ float g_O[NB * NT * NDM];
__device__ float g_covacc[NB * NT];
__device__ float g_W4[4][NDM * NDM];          // rounded Wq,Wk,Wv,Wo
__device__ float g_X[2][NB * NT * NDM];       // rounded query, memory

__global__ void zero_covacc_kernel() {
    int i = blockIdx.x * 256 + threadIdx.x;
    if (i < NB * NT) g_covacc[i] = 0.0f;
}

__device__ __forceinline__ uint32_t smem_u32(const void* p) {
    uint32_t a;
    asm("{ .reg .u64 t; cvta.to.shared.u64 t, %1; cvt.u32.u64 %0, t; }" : "=r"(a) : "l"(p));
    return a;
}
__device__ __forceinline__ uint32_t f2tf32(float x) {
    uint32_t r;
    asm("cvt.rna.tf32.f32 %0, %1;" : "=r"(r) : "f"(x));
    return r;
}
__device__ __forceinline__ float roundtf(float x) {
    return __uint_as_float(f2tf32(x));
}
__device__ __forceinline__ void mma_tf32(float c[4],
                                         uint32_t a0, uint32_t a1, uint32_t a2, uint32_t a3,
                                         uint32_t b0, uint32_t b1) {
    asm volatile(
        "mma.sync.aligned.m16n8k8.row.col.f32.tf32.tf32.f32 "
        "{%0,%1,%2,%3}, {%4,%5,%6,%7}, {%8,%9}, {%0,%1,%2,%3};"
        : "+f"(c[0]), "+f"(c[1]), "+f"(c[2]), "+f"(c[3])
        : "r"(a0), "r"(a1), "r"(a2), "r"(a3), "r"(b0), "r"(b1));
}

#define CP16(dst, src) \
    asm volatile("cp.async.cg.shared.global [%0], [%1], 16;" :: "r"(dst), "l"(src) : "memory")
#define CPC() asm volatile("cp.async.commit_group;" ::: "memory")
#define CPW(n) asm volatile("cp.async.wait_group %0;" :: "n"(n) : "memory")

// ---------------- pre-round inputs to tf32 ----------------
__global__ void round_inputs_kernel(
    const float4* __restrict__ Wq, const float4* __restrict__ Wk,
    const float4* __restrict__ Wv, const float4* __restrict__ Wo,
    const float4* __restrict__ q,  const float4* __restrict__ mem)
{
    int idx = blockIdx.x * 256 + threadIdx.x;
    if (idx >= 5242880) return;
    float4 v;
    float* dst;
    if (idx < 1048576) {
        int wi = idx >> 18;
        int off = idx & 0x3FFFF;
        const float4* src = (wi == 0) ? Wq : (wi == 1) ? Wk : (wi == 2) ? Wv : Wo;
        v = src[off];
        dst = &g_W4[wi][off * 4];
    } else {
        int j = idx - 1048576;
        int xi = j >> 21;
        int off = j & 0x1FFFFF;
        v = (xi == 0) ? q[off] : mem[off];
        dst = &g_X[xi][off * 4];
    }
    float4 r;
    r.x = roundtf(v.x); r.y = roundtf(v.y); r.z = roundtf(v.z); r.w = roundtf(v.w);
    *(float4*)dst = r;
}

// ================= tf32 GEMM, cp.async 3-stage (R12, unchanged) =============
#define G_SMEM_BYTES 61440

template <bool HEADED, bool ROUND_OUT>
__device__ __forceinline__ void gemm_body(
    const float* __restrict__ Ap, const float* __restrict__ W,
    const float* __restrict__ bias, float* __restrict__ dst,
    int bm, int bn)
{
    extern __shared__ float gsm[];
    float (*As)[128][20] = (float(*)[128][20])(gsm);
    float (*Ws)[128][20] = (float(*)[128][20])(gsm + 3 * 2560);
    uint32_t sbA = smem_u32(&As[0][0][0]);
    uint32_t sbW = smem_u32(&Ws[0][0][0]);

    int tid = threadIdx.x;
    int lane = tid & 31;
    int wid = tid >> 5;
    int warp_m = wid & 1;
    int warp_n = wid >> 1;
    int g = lane >> 2;
    int t = lane & 3;

    int lr = tid >> 1;
    int kc = (tid & 1) * 8;
    const float* aP = Ap + (size_t)(bm + lr) * NDM + kc;
    const float* wP = W  + (size_t)(bn + lr) * NDM + kc;
    uint32_t dA = sbA + (lr * 20 + kc) * 4;
    uint32_t dW = sbW + (lr * 20 + kc) * 4;

    float c[4][4][4];
#pragma unroll
    for (int mi = 0; mi < 4; mi++)
#pragma unroll
        for (int ni = 0; ni < 4; ni++)
#pragma unroll
            for (int e = 0; e < 4; e++) c[mi][ni][e] = 0.0f;

#pragma unroll
    for (int s = 0; s < 2; s++) {
        CP16(dA + s * 10240, aP + s * 16);
        CP16(dA + s * 10240 + 16, aP + s * 16 + 4);
        CP16(dW + s * 10240, wP + s * 16);
        CP16(dW + s * 10240 + 16, wP + s * 16 + 4);
        CPC();
    }

    for (int kt = 0; kt < 64; kt++) {
        if (kt < 63) { CPW(1); } else { CPW(0); }
        __syncthreads();
        int slot = kt - (kt / 3) * 3;

        if (kt + 2 < 64) {
            int ns = (kt + 2) - ((kt + 2) / 3) * 3;
            CP16(dA + ns * 10240, aP + (kt + 2) * 16);
            CP16(dA + ns * 10240 + 16, aP + (kt + 2) * 16 + 4);
            CP16(dW + ns * 10240, wP + (kt + 2) * 16);
            CP16(dW + ns * 10240 + 16, wP + (kt + 2) * 16 + 4);
            CPC();
        }

        const float (*Ac)[20] = As[slot];
        const float (*Wc)[20] = Ws[slot];
#pragma unroll
        for (int kk = 0; kk < 16; kk += 8) {
            uint32_t af[4][4];
#pragma unroll
            for (int mi = 0; mi < 4; mi++) {
                int r0 = warp_m * 64 + mi * 16 + g;
                af[mi][0] = __float_as_uint(Ac[r0][kk + t]);
                af[mi][1] = __float_as_uint(Ac[r0 + 8][kk + t]);
                af[mi][2] = __float_as_uint(Ac[r0][kk + t + 4]);
                af[mi][3] = __float_as_uint(Ac[r0 + 8][kk + t + 4]);
            }
            uint32_t bf[4][2];
#pragma unroll
            for (int ni = 0; ni < 4; ni++) {
                int c0 = warp_n * 32 + ni * 8 + g;
                bf[ni][0] = __float_as_uint(Wc[c0][kk + t]);
                bf[ni][1] = __float_as_uint(Wc[c0][kk + t + 4]);
            }
#pragma unroll
            for (int mi = 0; mi < 4; mi++)
#pragma unroll
                for (int ni = 0; ni < 4; ni++)
                    mma_tf32(c[mi][ni], af[mi][0], af[mi][1], af[mi][2], af[mi][3],
                             bf[ni][0], bf[ni][1]);
        }
    }

#pragma unroll
    for (int mi = 0; mi < 4; mi++) {
#pragma unroll
        for (int ni = 0; ni < 4; ni++) {
            int n0 = bn + warp_n * 32 + ni * 8 + t * 2;
            float b0v = __ldg(bias + n0);
            float b1v = __ldg(bias + n0 + 1);
#pragma unroll
            for (int rh = 0; rh < 2; rh++) {
                int m = bm + warp_m * 64 + mi * 16 + g + rh * 8;
                float v0 = c[mi][ni][rh * 2 + 0] + b0v;
                float v1 = c[mi][ni][rh * 2 + 1] + b1v;
                if (ROUND_OUT) { v0 = roundtf(v0); v1 = roundtf(v1); }
                if (HEADED) {
                    int bb = m >> 10, tok = m & 1023;
                    size_t base = (((size_t)(bb * NH + (n0 >> 6))) * NT + tok) * NHD + (n0 & 63);
                    dst[base] = v0; dst[base + 1] = v1;
                } else {
                    dst[(size_t)m * NDM + n0] = v0;
                    dst[(size_t)m * NDM + n0 + 1] = v1;
                }
            }
        }
    }
}

__global__ __launch_bounds__(256, 2) void qkv_gemm(
    const float* __restrict__ bq, const float* __restrict__ bk,
    const float* __restrict__ bv)
{
    int z = blockIdx.z;
    const float* A = (z == 0) ? g_X[0] : g_X[1];
    const float* W = g_W4[z];
    const float* bias = (z == 0) ? bq : (z == 1) ? bk : bv;
    float* dst = (z == 0) ? g_Q : (z == 1) ? g_K : g_V;
    gemm_body<true, true>(A, W, bias, dst, blockIdx.y * 128, blockIdx.x * 128);
}

__global__ __launch_bounds__(256, 2) void out_gemm(
    const float* __restrict__ bo, float* __restrict__ Cout)
{
    gemm_body<false, false>((const float*)g_O, g_W4[3], bo, Cout,
                            blockIdx.y * 128, blockIdx.x * 128);
}

// ================= fused attention: 32 q-rows/CTA, 64-token K+V tiles =======
// Per tile: S-MMA -> exp (in-loop l accumulation) -> P store -> PV-MMA.
// K stride 68 (S-phase conflict-free), V stride 72 (PV conflict-free).
#define SROW    1033
#define OFF_S   0                    // 32 x 1033 = 33056
#define OFF_K0  33056                // 64 x 68 = 4352
#define OFF_K1  37408                // 4352
#define OFF_V0  41760                // 64 x 72 = 4608
#define OFF_V1  46368                // 4608
#define OFF_QS  50976                // 32 x 68 = 2176
#define OFF_C   53152                // 1024
#define OFF_R   54176                // 32
#define OFF_L   54208                // 8 warps x 32 rows = 256
#define A_SMEM_FLOATS 54464
#define A_SMEM_BYTES  (A_SMEM_FLOATS * 4)   // 217856

__global__ __launch_bounds__(256) void attn_mma(
    const float* __restrict__ coverage, const float* __restrict__ Wcov)
{
    extern __shared__ float sm[];
    uint32_t sb = smem_u32(sm);
    int tid = threadIdx.x;
    int lane = tid & 31, wid = tid >> 5;
    int g = lane >> 2, t = lane & 3;
    int bh = blockIdx.y, b = bh >> 4, h = bh & 15;
    int q0 = blockIdx.x * 32;
    float wcov = Wcov[h];

    const float* Qb = g_Q + (size_t)bh * NT * NHD + (size_t)q0 * NHD;
    const float* Kb = g_K + (size_t)bh * NT * NHD;
    const float* Vb = g_V + (size_t)bh * NT * NHD;

    // ---- prologue: GA = {Q, cov, K0, V0}; GB = {K1, V1} ----
#pragma unroll
    for (int i = 0; i < 2; i++) {
        int id = tid + 256 * i;
        int q = id >> 4, c4 = id & 15;
        CP16(sb + (OFF_QS + q * 68 + c4 * 4) * 4, Qb + q * 64 + c4 * 4);
    }
    CP16(sb + (OFF_C + tid * 4) * 4, coverage + b * NT + tid * 4);
#pragma unroll
    for (int i = 0; i < 4; i++) {
        int id = tid + 256 * i;
        int tok = id >> 4, c4 = id & 15;
        CP16(sb + (OFF_K0 + tok * 68 + c4 * 4) * 4, Kb + tok * 64 + c4 * 4);
        CP16(sb + (OFF_V0 + tok * 72 + c4 * 4) * 4, Vb + tok * 64 + c4 * 4);
    }
    CPC();
#pragma unroll
    for (int i = 0; i < 4; i++) {
        int id = tid + 256 * i;
        int tok = id >> 4, c4 = id & 15;
        CP16(sb + (OFF_K1 + tok * 68 + c4 * 4) * 4, Kb + (64 + tok) * 64 + c4 * 4);
        CP16(sb + (OFF_V1 + tok * 72 + c4 * 4) * 4, Vb + (64 + tok) * 64 + c4 * 4);
    }
    CPC();
    CPW(1);
    __syncthreads();

    for (int i = tid; i < NT; i += 256) sm[OFF_C + i] *= wcov;

    // Q fragments (pre-rounded tf32 — raw bits); 2 m16 tiles (32 q-rows)
    uint32_t qf[2][8][4];
#pragma unroll
    for (int mi = 0; mi < 2; mi++)
#pragma unroll
        for (int kk = 0; kk < 8; kk++) {
            int base = OFF_QS + (mi * 16 + g) * 68 + kk * 8 + t;
            qf[mi][kk][0] = __float_as_uint(sm[base]);
            qf[mi][kk][1] = __float_as_uint(sm[base + 8 * 68]);
            qf[mi][kk][2] = __float_as_uint(sm[base + 4]);
            qf[mi][kk][3] = __float_as_uint(sm[base + 8 * 68 + 4]);
        }
    __syncthreads();

    // PV warp split + accumulators
    int mh = wid & 1, nh = (wid >> 1) & 1, kp = wid >> 2;   // kp in 0..1
    float oa[4][4];
#pragma unroll
    for (int nj = 0; nj < 4; nj++)
#pragma unroll
        for (int e = 0; e < 4; e++) oa[nj][e] = 0.0f;

    float l0 = 0.0f, l1 = 0.0f, l2 = 0.0f, l3 = 0.0f;   // rows g,g+8,g+16,g+24
    int tokb = wid * 8;

    // ================= fused main loop: 16 x 64-token tiles =================
    for (int kt = 0; kt < 16; kt++) {
        if (kt) {
            if (kt < 15) { CPW(1); } else { CPW(0); }
            __syncthreads();
            // V-buf[(kt+1)&1] free (tile kt-1 PV reads done) — issue V_{kt+1}
            if (kt <= 14) {
                uint32_t vof = ((kt + 1) & 1) ? OFF_V1 : OFF_V0;
#pragma unroll
                for (int i = 0; i < 4; i++) {
                    int id = tid + 256 * i;
                    int tok = id >> 4, c4 = id & 15;
                    CP16(sb + (vof + tok * 72 + c4 * 4) * 4,
                         Vb + ((kt + 1) * 64 + tok) * 64 + c4 * 4);
                }
                CPC();
            }
        }

        // ---- S-tile: warp owns 8 tokens; 2 m16 tiles; split even/odd chains
        {
            const float* Ks = sm + ((kt & 1) ? OFF_K1 : OFF_K0);
            const float* kr = Ks + (tokb + g) * 68 + t;
            float s0e[4] = {0, 0, 0, 0}, s0o[4] = {0, 0, 0, 0};
            float s1e[4] = {0, 0, 0, 0}, s1o[4] = {0, 0, 0, 0};
#pragma unroll
            for (int kk = 0; kk < 8; kk += 2) {
                uint32_t b0 = __float_as_uint(kr[kk * 8]);
                uint32_t b1 = __float_as_uint(kr[kk * 8 + 4]);
                uint32_t d0 = __float_as_uint(kr[kk * 8 + 8]);
                uint32_t d1 = __float_as_uint(kr[kk * 8 + 12]);
                mma_tf32(s0e, qf[0][kk][0], qf[0][kk][1], qf[0][kk][2], qf[0][kk][3], b0, b1);
                mma_tf32(s1e, qf[1][kk][0], qf[1][kk][1], qf[1][kk][2], qf[1][kk][3], b0, b1);
                mma_tf32(s0o, qf[0][kk+1][0], qf[0][kk+1][1], qf[0][kk+1][2], qf[0][kk+1][3], d0, d1);
                mma_tf32(s1o, qf[1][kk+1][0], qf[1][kk+1][1], qf[1][kk+1][2], qf[1][kk+1][3], d0, d1);
            }
            int kgl = kt * 64 + tokb + 2 * t;
            float cv0 = sm[OFF_C + kgl], cv1 = sm[OFF_C + kgl + 1];
            float e00 = __expf((s0e[0] + s0o[0]) * 0.125f + cv0);
            float e01 = __expf((s0e[1] + s0o[1]) * 0.125f + cv1);
            float e10 = __expf((s0e[2] + s0o[2]) * 0.125f + cv0);
            float e11 = __expf((s0e[3] + s0o[3]) * 0.125f + cv1);
            float e20 = __expf((s1e[0] + s1o[0]) * 0.125f + cv0);
            float e21 = __expf((s1e[1] + s1o[1]) * 0.125f + cv1);
            float e30 = __expf((s1e[2] + s1o[2]) * 0.125f + cv0);
            float e31 = __expf((s1e[3] + s1o[3]) * 0.125f + cv1);
            l0 += e00 + e01; l1 += e10 + e11; l2 += e20 + e21; l3 += e30 + e31;
            sm[OFF_S + g * SROW + kgl]            = roundtf(e00);
            sm[OFF_S + g * SROW + kgl + 1]        = roundtf(e01);
            sm[OFF_S + (g + 8) * SROW + kgl]      = roundtf(e10);
            sm[OFF_S + (g + 8) * SROW + kgl + 1]  = roundtf(e11);
            sm[OFF_S + (g + 16) * SROW + kgl]     = roundtf(e20);
            sm[OFF_S + (g + 16) * SROW + kgl + 1] = roundtf(e21);
            sm[OFF_S + (g + 24) * SROW + kgl]     = roundtf(e30);
            sm[OFF_S + (g + 24) * SROW + kgl + 1] = roundtf(e31);
        }
        __syncthreads();   // P-tile visible; K[kt&1] reads done

        // K-buf[kt&1] free — issue K_{kt+2}
        if (kt < 14) {
            uint32_t kof = (kt & 1) ? OFF_K1 : OFF_K0;
#pragma unroll
            for (int i = 0; i < 4; i++) {
                int id = tid + 256 * i;
                int tok = id >> 4, c4 = id & 15;
                CP16(sb + (kof + tok * 68 + c4 * 4) * 4,
                     Kb + ((kt + 2) * 64 + tok) * 64 + c4 * 4);
            }
            CPC();
        }

        // ---- PV-tile: 8 k-steps split 2-way by kp; 4 n8-tiles per warp ----
        {
            const float* Vs = sm + ((kt & 1) ? OFF_V1 : OFF_V0);
#pragma unroll
            for (int s = 0; s < 4; s++) {
                int kb = (s * 2 + kp) * 8;
                int ar = OFF_S + (mh * 16 + g) * SROW + kt * 64 + kb + t;
                uint32_t a0 = __float_as_uint(sm[ar]);
                uint32_t a1 = __float_as_uint(sm[ar + 8 * SROW]);
                uint32_t a2 = __float_as_uint(sm[ar + 4]);
                uint32_t a3 = __float_as_uint(sm[ar + 8 * SROW + 4]);
#pragma unroll
                for (int nj = 0; nj < 4; nj++) {
                    int d0 = nh * 32 + nj * 8 + g;
                    uint32_t b0 = __float_as_uint(Vs[(kb + t) * 72 + d0]);
                    uint32_t b1 = __float_as_uint(Vs[(kb + t + 4) * 72 + d0]);
                    mma_tf32(oa[nj], a0, a1, a2, a3, b0, b1);
                }
            }
        }
    }

    // ---- row-sum reduction: shuffle across t, then across warps via smem ----
    l0 += __shfl_xor_sync(0xffffffff, l0, 1); l0 += __shfl_xor_sync(0xffffffff, l0, 2);
    l1 += __shfl_xor_sync(0xffffffff, l1, 1); l1 += __shfl_xor_sync(0xffffffff, l1, 2);
    l2 += __shfl_xor_sync(0xffffffff, l2, 1); l2 += __shfl_xor_sync(0xffffffff, l2, 2);
    l3 += __shfl_xor_sync(0xffffffff, l3, 1); l3 += __shfl_xor_sync(0xffffffff, l3, 2);
    if (t == 0) {
        sm[OFF_L + wid * 32 + g]      = l0;
        sm[OFF_L + wid * 32 + g + 8]  = l1;
        sm[OFF_L + wid * 32 + g + 16] = l2;
        sm[OFF_L + wid * 32 + g + 24] = l3;
    }
    __syncthreads();
    if (tid < 32) {
        float s = 0.0f;
#pragma unroll
        for (int w = 0; w < 8; w++) s += sm[OFF_L + w * 32 + tid];
        sm[OFF_R + tid] = 1.0f / s;
    }
    __syncthreads();

    // ---- coverage column sums ----
    for (int k = tid; k < NT; k += 256) {
        float s = 0.0f;
#pragma unroll 8
        for (int q = 0; q < 32; q++)
            s += sm[OFF_S + q * SROW + k] * sm[OFF_R + q];
        atomicAdd(&g_covacc[b * NT + k], s);
    }

    // ---- 2-way kp partial reduction + output (reuses K-buffer region) ----
    {
        float* op = sm + OFF_K0 + kp * 2176;
        int rb = mh * 16 + g;
#pragma unroll
        for (int nj = 0; nj < 4; nj++) {
            int col = nh * 32 + nj * 8 + 2 * t;
            op[rb * 68 + col]           = oa[nj][0];
            op[rb * 68 + col + 1]       = oa[nj][1];
            op[(rb + 8) * 68 + col]     = oa[nj][2];
            op[(rb + 8) * 68 + col + 1] = oa[nj][3];
        }
    }
    __syncthreads();
#pragma unroll
    for (int e = 0; e < 8; e++) {
        int idx = tid + e * 256;
        int q = idx >> 6, d = idx & 63;
        float val = (sm[OFF_K0 + q * 68 + d] + sm[OFF_K0 + 2176 + q * 68 + d])
                    * sm[OFF_R + q];
        g_O[((size_t)(b * NT + q0 + q)) * NDM + h * 64 + d] = roundtf(val);
    }
}

__global__ void finalize_cov_kernel(const float* __restrict__ coverage,
                                    float* __restrict__ outcov)
{
    int i = blockIdx.x * 256 + threadIdx.x;
    if (i < NB * NT) outcov[i] = coverage[i] + g_covacc[i] * (1.0f / NH);
}

// ================= launcher =================
extern "C" void kernel_launch(void* const* d_in, const int* in_sizes, int n_in,
                              void* d_out, int out_size)
{
    const float* query    = (const float*)d_in[0];
    const float* memory   = (const float*)d_in[1];
    const float* coverage = (const float*)d_in[2];
    const float* Wq       = (const float*)d_in[3];
    const float* bq       = (const float*)d_in[4];
    const float* Wk       = (const float*)d_in[5];
    const float* bk       = (const float*)d_in[6];
    const float* Wv       = (const float*)d_in[7];
    const float* bv       = (const float*)d_in[8];
    const float* Wo       = (const float*)d_in[9];
    const float* bo       = (const float*)d_in[10];
    const float* Wcov     = (const float*)d_in[11];
    float* out = (float*)d_out;

    cudaFuncSetAttribute(qkv_gemm, cudaFuncAttributeMaxDynamicSharedMemorySize, G_SMEM_BYTES);
    cudaFuncSetAttribute(out_gemm, cudaFuncAttributeMaxDynamicSharedMemorySize, G_SMEM_BYTES);
    cudaFuncSetAttribute(attn_mma, cudaFuncAttributeMaxDynamicSharedMemorySize, A_SMEM_BYTES);

    zero_covacc_kernel<<<32, 256>>>();

    round_inputs_kernel<<<(5242880 + 255) / 256, 256>>>(
        (const float4*)Wq, (const float4*)Wk, (const float4*)Wv, (const float4*)Wo,
        (const float4*)query, (const float4*)memory);

    qkv_gemm<<<dim3(NDM / 128, (NB * NT) / 128, 3), 256, G_SMEM_BYTES>>>(bq, bk, bv);

    attn_mma<<<dim3(NT / 32, NB * NH), 256, A_SMEM_BYTES>>>(coverage, Wcov);

    out_gemm<<<dim3(NDM / 128, (NB * NT) / 128), 256, G_SMEM_BYTES>>>(bo, out);

    finalize_cov_kernel<<<32, 256>>>(coverage, out + (size_t)NB * NT * NDM);
}